// round 12
// baseline (speedup 1.0000x reference)
#include <cuda_runtime.h>
#include <cstdint>

// Detail loss, simplified:
//   D = sum_c (infer - ref)   per image plane
//   out = (sum|D[w+1]-D[w-1]| + sum|D[h+1]-D[h-1]|) * 0.25 / (98*258*256)
// cp.async deep pipeline: each warp owns a 32-row x 128-col tile (4 cols/lane),
// raw rows are cp.async'd (LDGSTS) into a per-warp 4-slot smem ring, 3 rows in
// flight, sequenced with per-thread commit_group/wait_group (each lane consumes
// only bytes it copied -> no barriers, no mbarriers). In-flight bytes/SM ~95KB
// (vs ~30KB register-resident before) -> latency/queueing fully hidden.
// Serpentine row walk keeps the 6% halo rows in L2.

#define NIMG   98            // 2*7*7
#define IMG_H  256
#define IMG_W  256
#define RSTRIP 32            // rows per warp tile
#define VSTRIPS (IMG_H / RSTRIP)           // 8
#define HALVES  2                          // 128-col halves
#define NWARPS (NIMG * VSTRIPS * HALVES)   // 1568
#define WPB    2
#define NBLOCKS (NWARPS / WPB)             // 784
#define PLANE  (IMG_H * IMG_W)

// Per-warp smem ring: 4 slots x (6 planes x 128 floats) + 4 seam slots x 8 floats
#define NSLOT  4
#define PL_F   128                 // floats per plane-row chunk (128 cols)
#define ROW_F  (6 * PL_F)          // 768 floats per slot
#define SEAM_F (NSLOT * ROW_F)     // seam area starts here (floats)
#define WARP_F (SEAM_F + NSLOT * 8)          // 3104 floats per warp
#define SMEM_BYTES (WPB * WARP_F * 4)        // 24832 B per block

#define CP_ASYNC_16(dst, src) \
    asm volatile("cp.async.cg.shared.global [%0], [%1], 16;" :: "r"(dst), "l"(src))
#define CP_ASYNC_4(dst, src) \
    asm volatile("cp.async.ca.shared.global [%0], [%1], 4;" :: "r"(dst), "l"(src))
#define CP_COMMIT() asm volatile("cp.async.commit_group;" ::: "memory")
#define CP_WAIT(N)  asm volatile("cp.async.wait_group %0;" :: "n"(N) : "memory")

__device__ float        g_partials[NWARPS];
__device__ unsigned int g_count;   // zero-init; reset each launch by last block

__device__ __forceinline__ uint32_t smem_u32(const void* p) {
    return (uint32_t)__cvta_generic_to_shared(p);
}

// Issue cp.async for one raw row (6 plane chunks of 16B per lane + seam 4B x6
// from lane 0). ALWAYS commits a group (possibly empty) to keep per-thread
// group counting uniform.
__device__ __forceinline__ void issue_row(uint32_t wsm,
                                          const float* __restrict__ pi,
                                          const float* __restrict__ pr,
                                          int rt, int slot, int lane,
                                          int col0, int seamcol, bool valid) {
    if (valid) {
        const size_t off = (size_t)rt * IMG_W + col0 + lane * 4;
        const uint32_t dst = wsm + slot * (ROW_F * 4) + lane * 16;
        #pragma unroll
        for (int c = 0; c < 3; c++) {
            CP_ASYNC_16(dst + c * (PL_F * 4),       pi + (size_t)c * PLANE + off);
            CP_ASYNC_16(dst + (c + 3) * (PL_F * 4), pr + (size_t)c * PLANE + off);
        }
        if (lane == 0) {
            const size_t soff = (size_t)rt * IMG_W + seamcol;
            const uint32_t sd = wsm + SEAM_F * 4 + slot * 32;
            #pragma unroll
            for (int c = 0; c < 3; c++) {
                CP_ASYNC_4(sd + c * 4,      pi + (size_t)c * PLANE + soff);
                CP_ASYNC_4(sd + 12 + c * 4, pr + (size_t)c * PLANE + soff);
            }
        }
    }
    CP_COMMIT();
}

// Build D values (4 cols) + seam D for one smem slot.
__device__ __forceinline__ void combine(const float* __restrict__ wsf, int slot,
                                        int lane, bool valid,
                                        float d[4], float& ds) {
    if (valid) {
        const float4* p = (const float4*)(wsf + slot * ROW_F) + lane;
        float4 v[6];
        #pragma unroll
        for (int c = 0; c < 6; c++) v[c] = p[c * (PL_F / 4)];
        d[0] = (v[0].x - v[3].x) + (v[1].x - v[4].x) + (v[2].x - v[5].x);
        d[1] = (v[0].y - v[3].y) + (v[1].y - v[4].y) + (v[2].y - v[5].y);
        d[2] = (v[0].z - v[3].z) + (v[1].z - v[4].z) + (v[2].z - v[5].z);
        d[3] = (v[0].w - v[3].w) + (v[1].w - v[4].w) + (v[2].w - v[5].w);
        const float* s = wsf + SEAM_F + slot * 8;   // uniform addr -> broadcast
        ds = (s[0] - s[3]) + (s[1] - s[4]) + (s[2] - s[5]);
    } else {
        d[0] = d[1] = d[2] = d[3] = 0.f;
        ds = 0.f;
    }
}

__global__ void __launch_bounds__(WPB * 32)
detail_kernel(const float* __restrict__ infer, const float* __restrict__ ref,
              float* __restrict__ out) {
    extern __shared__ float smem[];
    const int tid   = threadIdx.x;
    const int lane  = tid & 31;
    const int warp  = tid >> 5;
    const int gw    = blockIdx.x * WPB + warp;
    const int n     = gw >> 4;                 // / (VSTRIPS*HALVES)
    const int rem   = gw & 15;
    const int strip = rem >> 1;
    const int half  = rem & 1;
    const int r0    = strip * RSTRIP;
    const int col0    = half * 128;
    const int seamcol = half ? 127 : 128;

    // Serpentine: odd strips walk bottom->top so strip-boundary rows are read
    // by both neighbors at the same time (L2 hit; DRAM stays at byte floor).
    const int dir    = (strip & 1) ? -1 : 1;
    const int gstart = (strip & 1) ? (r0 + RSTRIP - 1) : r0;

    const float* pi = infer + (size_t)n * 3 * PLANE;
    const float* pr = ref   + (size_t)n * 3 * PLANE;

    float* wsf = smem + warp * WARP_F;
    const uint32_t wsm = smem_u32(wsf);

    // Row t (t = -1..RSTRIP) lives in slot (t+1)&3; group id = t+2.
    // Prologue: issue t=-1,0,1,2.
    const int rtm1 = gstart - dir;
    const bool vm1 = (unsigned)rtm1 < IMG_H;
    issue_row(wsm, pi, pr, rtm1,             0, lane, col0, seamcol, vm1);
    issue_row(wsm, pi, pr, gstart,           1, lane, col0, seamcol, true);
    issue_row(wsm, pi, pr, gstart + dir,     2, lane, col0, seamcol, true);
    issue_row(wsm, pi, pr, gstart + 2 * dir, 3, lane, col0, seamcol, true);

    float pm[4], pc[4], pn[4];
    float es_d, es_c, es_n;

    CP_WAIT(3);                                   // row -1 ready
    combine(wsf, 0, lane, vm1, pm, es_d);
    CP_WAIT(2);                                   // row 0 ready
    combine(wsf, 1, lane, true, pc, es_c);
    issue_row(wsm, pi, pr, gstart + 3 * dir, 0, lane, col0, seamcol, true); // t=3

    float sum = 0.f;

    #pragma unroll 4
    for (int h = 0; h < RSTRIP; h++) {
        // Row t=h+1 is in group h+3; committed so far = 5+h -> wait_group 2.
        CP_WAIT(2);
        combine(wsf, (h + 2) & 3, lane, true, pn, es_n);

        // Issue row t=h+4 into the slot just vacated by row h (already in regs).
        const int tnext = h + 4;
        issue_row(wsm, pi, pr, gstart + tnext * dir, (tnext + 1) & 3,
                  lane, col0, seamcol, tnext <= RSTRIP);

        // Horizontal gradient on row g=gstart+h*dir (values in pc).
        float l = __shfl_up_sync(0xffffffffu,  pc[3], 1);
        float r = __shfl_down_sync(0xffffffffu, pc[0], 1);
        if (lane == 0)  l = half ? es_c : 0.f;   // seam D[127] or image edge
        if (lane == 31) r = half ? 0.f  : es_c;  // image edge or seam D[128]
        sum += fabsf(pc[1] - l);
        sum += fabsf(pc[2] - pc[0]);
        sum += fabsf(pc[3] - pc[1]);
        sum += fabsf(r - pc[2]);

        // Vertical gradient: |D[g+dir] - D[g-dir]| == |D[g+1]-D[g-1]|.
        #pragma unroll
        for (int j = 0; j < 4; j++) sum += fabsf(pn[j] - pm[j]);

        // Roll the window.
        #pragma unroll
        for (int j = 0; j < 4; j++) { pm[j] = pc[j]; pc[j] = pn[j]; }
        es_c = es_n;
    }

    // Warp reduction.
    #pragma unroll
    for (int off = 16; off > 0; off >>= 1)
        sum += __shfl_down_sync(0xffffffffu, sum, off);

    __shared__ bool is_last;
    if (lane == 0) {
        g_partials[gw] = sum;
        __threadfence();
    }
    __syncthreads();
    if (tid == 0)
        is_last = (atomicAdd(&g_count, 1u) == NBLOCKS - 1);
    __syncthreads();

    if (is_last) {
        float t = 0.f;
        for (int i = tid; i < NWARPS; i += WPB * 32)
            t += __ldcg(&g_partials[i]);
        #pragma unroll
        for (int off = 16; off > 0; off >>= 1)
            t += __shfl_down_sync(0xffffffffu, t, off);
        __shared__ float wsum[WPB];
        if (lane == 0) wsum[tid >> 5] = t;
        __syncthreads();
        if (tid == 0) {
            float u = 0.f;
            #pragma unroll
            for (int i = 0; i < WPB; i++) u += wsum[i];
            // 0.5 (gradient coeff) * 0.5 (avg of two losses) / (98*258*256)
            out[0] = u * (0.25f / 6472704.0f);
            g_count = 0;   // deterministic across graph replays
        }
    }
}

extern "C" void kernel_launch(void* const* d_in, const int* in_sizes, int n_in,
                              void* d_out, int out_size) {
    const float* infer = (const float*)d_in[0];
    const float* ref   = (const float*)d_in[1];
    detail_kernel<<<NBLOCKS, WPB * 32, SMEM_BYTES>>>(infer, ref, (float*)d_out);
}

// round 13
// speedup vs baseline: 1.1199x; 1.1199x over previous
#include <cuda_runtime.h>

// Detail loss, simplified:
//   D = sum_c (infer - ref)   per image plane
//   out = (sum|D[w+1]-D[w-1]| + sum|D[h+1]-D[h-1]|) * 0.25 / (98*258*256)
// Combination of every measured win:
//  - 8 cols/lane, warp-per-(16-row x 256-col) tile: 12 LDG.128 per row, no seam
//  - TWO live row buffers (one-row-ahead, ~24 LDG in flight/warp): R8 showed
//    achieved DRAM BW still grows with in-flight depth at this level
//  - serpentine strip walk: strip-boundary halo rows read concurrently by both
//    neighbors -> L2 hits, DRAM stays at the 154MB mandatory floor
//  - regs capped via launch_bounds(64,8): 16 warps/SM capacity >= 10.6 needed
//    -> guaranteed single wave, no tail

#define NIMG   98            // 2*7*7
#define IMG_H  256
#define IMG_W  256
#define RSTRIP 16            // rows per warp tile
#define VSTRIPS (IMG_H / RSTRIP)         // 16
#define NWARPS (NIMG * VSTRIPS)          // 1568
#define WPB    2
#define NBLOCKS (NWARPS / WPB)           // 784
#define PLANE  (IMG_H * IMG_W)

__device__ float        g_partials[NWARPS];
__device__ unsigned int g_count;     // zero-init; reset each launch by last block

struct Raw {
    float4 a[6];   // infer: 3 channels x 2 float4
    float4 b[6];   // ref
};

__device__ __forceinline__ void issue_load(const float* __restrict__ pi,
                                           const float* __restrict__ pr,
                                           int row, int lane, bool valid, Raw& r) {
    if (valid) {
        const size_t off = (size_t)row * IMG_W + lane * 8;
        #pragma unroll
        for (int c = 0; c < 3; c++) {
            const float* a = pi + (size_t)c * PLANE + off;
            const float* b = pr + (size_t)c * PLANE + off;
            r.a[c * 2]     = *(const float4*)a;
            r.a[c * 2 + 1] = *(const float4*)(a + 4);
            r.b[c * 2]     = *(const float4*)b;
            r.b[c * 2 + 1] = *(const float4*)(b + 4);
        }
    } else {
        const float4 z = make_float4(0.f, 0.f, 0.f, 0.f);
        #pragma unroll
        for (int i = 0; i < 6; i++) { r.a[i] = z; r.b[i] = z; }
    }
}

__device__ __forceinline__ void combine(const Raw& r, float d[8]) {
    #pragma unroll
    for (int j = 0; j < 8; j++) d[j] = 0.f;
    #pragma unroll
    for (int c = 0; c < 3; c++) {
        const float4 a0 = r.a[c * 2], a1 = r.a[c * 2 + 1];
        const float4 b0 = r.b[c * 2], b1 = r.b[c * 2 + 1];
        d[0] += a0.x - b0.x;  d[1] += a0.y - b0.y;
        d[2] += a0.z - b0.z;  d[3] += a0.w - b0.w;
        d[4] += a1.x - b1.x;  d[5] += a1.y - b1.y;
        d[6] += a1.z - b1.z;  d[7] += a1.w - b1.w;
    }
}

__global__ void __launch_bounds__(WPB * 32, 8)
detail_kernel(const float* __restrict__ infer, const float* __restrict__ ref,
              float* __restrict__ out) {
    const int tid   = threadIdx.x;
    const int lane  = tid & 31;
    const int gw    = blockIdx.x * WPB + (tid >> 5);   // global warp id
    const int n     = gw >> 4;                          // / VSTRIPS
    const int strip = gw & 15;
    const int r0    = strip * RSTRIP;

    // Serpentine: even strips walk top->bottom, odd strips bottom->top, so
    // rows shared across a strip boundary are read at the same time (L2 hit).
    const int dir    = (strip & 1) ? -1 : 1;
    const int gstart = (strip & 1) ? (r0 + RSTRIP - 1) : r0;

    const float* pi = infer + (size_t)n * 3 * PLANE;
    const float* pr = ref   + (size_t)n * 3 * PLANE;

    // Prologue: rows gstart-dir, gstart combined now; row gstart+dir in flight.
    Raw buf[2], rtop, rcur;
    {
        const int rA = gstart - dir;
        issue_load(pi, pr, rA, lane, (unsigned)rA < IMG_H, rtop);
    }
    issue_load(pi, pr, gstart,       lane, true, rcur);
    issue_load(pi, pr, gstart + dir, lane, true, buf[1]);   // consumed at h=0

    float pm[8], pc[8], pn[8];        // rows g-dir, g, g+dir
    combine(rtop, pm);
    combine(rcur, pc);

    float sum = 0.f;

    #pragma unroll 2
    for (int h = 0; h < RSTRIP; h++) {
        const int g = gstart + h * dir;

        // Issue loads for row g+2*dir BEFORE consuming row g+dir (one-ahead,
        // two live buffers -> ~24 LDG.128 in flight per warp).
        const int rnext = g + 2 * dir;
        issue_load(pi, pr, rnext, lane,
                   (h + 1 < RSTRIP) && ((unsigned)rnext < IMG_H), buf[h & 1]);

        combine(buf[(h + 1) & 1], pn);   // row g+dir, issued last iteration

        // Horizontal gradient on row g (values in pc; 8 cols per lane).
        float l = __shfl_up_sync(0xffffffffu,  pc[7], 1);
        float r = __shfl_down_sync(0xffffffffu, pc[0], 1);
        if (lane == 0)  l = 0.f;   // image edge: zero padding
        if (lane == 31) r = 0.f;
        sum += fabsf(pc[1] - l);
        #pragma unroll
        for (int j = 1; j < 7; j++) sum += fabsf(pc[j + 1] - pc[j - 1]);
        sum += fabsf(r - pc[6]);

        // Vertical gradient: |D[g+dir]-D[g-dir]| = |D[g+1]-D[g-1]|.
        #pragma unroll
        for (int j = 0; j < 8; j++) sum += fabsf(pn[j] - pm[j]);

        // Roll the window.
        #pragma unroll
        for (int j = 0; j < 8; j++) { pm[j] = pc[j]; pc[j] = pn[j]; }
    }

    // Warp reduction.
    #pragma unroll
    for (int off = 16; off > 0; off >>= 1)
        sum += __shfl_down_sync(0xffffffffu, sum, off);

    __shared__ bool is_last;
    if (lane == 0) {
        g_partials[gw] = sum;
        __threadfence();
    }
    __syncthreads();
    if (tid == 0)
        is_last = (atomicAdd(&g_count, 1u) == NBLOCKS - 1);
    __syncthreads();

    if (is_last) {
        float t = 0.f;
        #pragma unroll 4
        for (int i = tid; i < NWARPS; i += WPB * 32)
            t += __ldcg(&g_partials[i]);
        #pragma unroll
        for (int off = 16; off > 0; off >>= 1)
            t += __shfl_down_sync(0xffffffffu, t, off);
        __shared__ float wsum[WPB];
        if (lane == 0) wsum[tid >> 5] = t;
        __syncthreads();
        if (tid == 0) {
            float u = 0.f;
            #pragma unroll
            for (int i = 0; i < WPB; i++) u += wsum[i];
            // 0.5 (gradient coeff) * 0.5 (avg of two losses) / (98*258*256)
            out[0] = u * (0.25f / 6472704.0f);
            g_count = 0;   // deterministic across graph replays
        }
    }
}

extern "C" void kernel_launch(void* const* d_in, const int* in_sizes, int n_in,
                              void* d_out, int out_size) {
    const float* infer = (const float*)d_in[0];
    const float* ref   = (const float*)d_in[1];
    detail_kernel<<<NBLOCKS, WPB * 32>>>(infer, ref, (float*)d_out);
}